// round 5
// baseline (speedup 1.0000x reference)
#include <cuda_runtime.h>
#include <cuda_bf16.h>

// Problem constants (from reference)
#define BATCH  16
#define MCTRL  64
#define NCTRL  64
#define LKNOT  68      // M + P + 1
#define DEG    3
#define TOUT   256     // OUT_U == OUT_V
#define RPB    8       // u-rows per block
#define THREADS 512
#define BPB    (TOUT / RPB)   // 32 blocks per batch

// Span binary search: reference's first-occurrence argmin over masked diffs
// equals the last index s with (traw - U[s+DEG] > thr), or 0 if none.
__device__ __forceinline__ int find_span(const float* __restrict__ U,
                                         float traw, float thr)
{
    int c = 0;
    #pragma unroll
    for (int step = 32; step >= 1; step >>= 1) {
        int nc = c + step;
        if (nc <= 62 && (traw - U[nc - 1 + DEG]) > thr) c = nc;
    }
    int bi = c - 1;
    if (bi < 0) bi = 0;
    int span = bi + DEG;
    if (span > MCTRL - 1) span = MCTRL - 1;
    return span;
}

// Degree-3 Cox-de Boor on raw (unnormalized) knots — affine invariant.
__device__ __forceinline__ float4 cox_de_boor(const float* __restrict__ U,
                                              float t, int span)
{
    float Nb[DEG + 1];
    Nb[0] = 1.f;
    #pragma unroll
    for (int k = 1; k <= DEG; k++) {
        float saved = 0.f;
        #pragma unroll
        for (int r = 0; r < DEG; r++) {
            if (r >= k) break;
            float K1   = U[span + r + 1];
            float K2   = U[span + 1 - k + r];
            float temp = Nb[r] / ((K1 - t) + (t - K2));
            Nb[r]  = saved + (K1 - t) * temp;
            saved  = (t - K2) * temp;
        }
        Nb[k] = saved;
    }
    return make_float4(Nb[0], Nb[1], Nb[2], Nb[3]);
}

// ---------------------------------------------------------------------------
// Fused kernel: parallel knot cumsum + span binary-search + Cox-de Boor +
// factorized tensor-product evaluation. Single launch, 512 thr, 8 rows/block.
// u and v grids are identical (reference builds V from knot_u too), so the
// basis at parameter index p serves both roles.
// ---------------------------------------------------------------------------
__global__ __launch_bounds__(THREADS, 3) void SurfEval_fused_kernel(
    const float4* __restrict__ ctrl,   // [B][64][64] float4 (x,y,z,w)
    const float*  __restrict__ knot_u, // [B][68]
    float*        __restrict__ out)    // [B][256][256][3]
{
    const int b    = blockIdx.x / BPB;
    const int i0   = (blockIdx.x % BPB) * RPB;
    const int tid  = threadIdx.x;
    const int lane = tid & 31;
    const int wid  = tid >> 5;

    __shared__ float  U[LKNOT];
    __shared__ float  warpsum[2];
    __shared__ float4 basis_sh[TOUT];        // 4 KB (rows i0..i0+7 read back)
    __shared__ float  colsx[RPB][NCTRL];     // 2 KB each
    __shared__ float  colsy[RPB][NCTRL];
    __shared__ float  colsz[RPB][NCTRL];

    // ---- parallel inclusive cumsum of the 68 raw knot increments ----
    {
        float v = (tid < LKNOT) ? knot_u[b * LKNOT + tid] : 0.f;
        if (wid < 3) {
            #pragma unroll
            for (int off = 1; off < 32; off <<= 1) {
                float n = __shfl_up_sync(0xffffffffu, v, off);
                if (lane >= off) v += n;
            }
            if (lane == 31 && wid < 2) warpsum[wid] = v;
        }
        __syncthreads();
        if (wid == 1)      v += warpsum[0];
        else if (wid == 2) v += warpsum[0] + warpsum[1];
        if (tid < LKNOT) U[tid] = v;
        __syncthreads();
    }

    const float c0  = U[0];
    const float den = U[LKNOT - 1] - c0;
    const float thr = 1e-8f * den;
    const float step01 = (float)((1.0 - 2e-5) / 255.0);

    // ---- phase-1 addressing: row span first, issue ctrl loads ASAP ----
    const int ri = tid >> 6;            // 0..7
    const int cc = tid & 63;            // 0..63
    const int i  = i0 + ri;

    const float t_row = c0 + fmaf((float)i, step01, 1e-5f) * den;
    const int   srow  = find_span(U, t_row, thr) - 3;

    const float4* cp = ctrl + ((size_t)(b * MCTRL) + srow) * NCTRL + cc;
    float4 p0 = cp[0 * NCTRL];
    float4 p1 = cp[1 * NCTRL];
    float4 p2 = cp[2 * NCTRL];
    float4 p3 = cp[3 * NCTRL];

    // ---- own (v-role) span + basis, overlapped with ctrl loads in flight ----
    const int   j     = tid & (TOUT - 1);            // output column
    const float t_own = c0 + fmaf((float)j, step01, 1e-5f) * den;
    const int   sj    = find_span(U, t_own, thr) - 3;
    const float4 nv   = cox_de_boor(U, t_own, sj + 3);

    if (tid < TOUT) basis_sh[tid] = nv;
    __syncthreads();

    // ---- phase 1: u-contraction for (row ri, ctrl column cc) ----
    {
        const float4 nu = basis_sh[i];
        colsx[ri][cc] = fmaf(nu.x, p0.x, fmaf(nu.y, p1.x, fmaf(nu.z, p2.x, nu.w * p3.x)));
        colsy[ri][cc] = fmaf(nu.x, p0.y, fmaf(nu.y, p1.y, fmaf(nu.z, p2.y, nu.w * p3.y)));
        colsz[ri][cc] = fmaf(nu.x, p0.z, fmaf(nu.y, p1.z, fmaf(nu.z, p2.z, nu.w * p3.z)));
    }
    __syncthreads();

    // ---- phase 2: v-contraction (basis in regs). Each thread: 4 rows, col j.
    const int rbase = (tid >> 8) * 4;   // 0 or 4
    #pragma unroll
    for (int rr = 0; rr < 4; rr++) {
        const int r = rbase + rr;
        float x = fmaf(nv.x, colsx[r][sj],
                  fmaf(nv.y, colsx[r][sj + 1],
                  fmaf(nv.z, colsx[r][sj + 2], nv.w * colsx[r][sj + 3])));
        float y = fmaf(nv.x, colsy[r][sj],
                  fmaf(nv.y, colsy[r][sj + 1],
                  fmaf(nv.z, colsy[r][sj + 2], nv.w * colsy[r][sj + 3])));
        float z = fmaf(nv.x, colsz[r][sj],
                  fmaf(nv.y, colsz[r][sj + 1],
                  fmaf(nv.z, colsz[r][sj + 2], nv.w * colsz[r][sj + 3])));

        float* o = out + ((size_t)((b * TOUT) + i0 + r) * TOUT + j) * 3;
        o[0] = x;
        o[1] = y;
        o[2] = z;
    }
}

// ---------------------------------------------------------------------------
// Launch. Inputs: d_in[0]=ctrl_pts [16,64,64,4] f32, d_in[1]=knot_u [16,68],
// d_in[2]=knot_v (UNUSED — reference builds V from knot_u).
// Output: [16,256,256,3] f32.
// ---------------------------------------------------------------------------
extern "C" void kernel_launch(void* const* d_in, const int* in_sizes, int n_in,
                              void* d_out, int out_size)
{
    const float4* ctrl   = (const float4*)d_in[0];
    const float*  knot_u = (const float*) d_in[1];
    float*        out    = (float*)d_out;

    SurfEval_fused_kernel<<<BATCH * BPB, THREADS>>>(ctrl, knot_u, out);
}

// round 6
// speedup vs baseline: 1.3732x; 1.3732x over previous
#include <cuda_runtime.h>
#include <cuda_bf16.h>

// Problem constants (from reference)
#define BATCH  16
#define MCTRL  64
#define NCTRL  64
#define LKNOT  68      // M + P + 1
#define DEG    3
#define TOUT   256     // OUT_U == OUT_V
#define RPB    8       // u-rows per block
#define THREADS 256
#define BPB    (TOUT / RPB)   // 32 blocks per batch

// Span binary search: reference's first-occurrence argmin over masked diffs
// equals the last index s with (traw - U[s+DEG] > thr), or 0 if none.
__device__ __forceinline__ int find_span(const float* __restrict__ U,
                                         float traw, float thr)
{
    int c = 0;
    #pragma unroll
    for (int step = 32; step >= 1; step >>= 1) {
        int nc = c + step;
        if (nc <= 62 && (traw - U[nc - 1 + DEG]) > thr) c = nc;
    }
    int bi = c - 1;
    if (bi < 0) bi = 0;
    int span = bi + DEG;
    if (span > MCTRL - 1) span = MCTRL - 1;
    return span;
}

// Degree-3 Cox-de Boor on raw (unnormalized) knots — affine invariant.
// Fast division: tolerance is 1e-3, current margin ~400x.
__device__ __forceinline__ float4 cox_de_boor(const float* __restrict__ U,
                                              float t, int span)
{
    float Nb[DEG + 1];
    Nb[0] = 1.f;
    #pragma unroll
    for (int k = 1; k <= DEG; k++) {
        float saved = 0.f;
        #pragma unroll
        for (int r = 0; r < DEG; r++) {
            if (r >= k) break;
            float K1   = U[span + r + 1];
            float K2   = U[span + 1 - k + r];
            float temp = __fdividef(Nb[r], (K1 - t) + (t - K2));
            Nb[r]  = saved + (K1 - t) * temp;
            saved  = (t - K2) * temp;
        }
        Nb[k] = saved;
    }
    return make_float4(Nb[0], Nb[1], Nb[2], Nb[3]);
}

// ---------------------------------------------------------------------------
// Fused kernel, minimal-barrier version. 256 threads, 8 u-rows per block.
// After the knot scan there is exactly ONE block barrier (cols publish):
// phase-1 threads recompute their row's u-basis locally instead of reading a
// shared basis table, so ctrl loads depend only on the scan result.
// u and v grids are identical (reference builds V from knot_u too).
// ---------------------------------------------------------------------------
__global__ __launch_bounds__(THREADS, 6) void SurfEval_fused_kernel(
    const float4* __restrict__ ctrl,   // [B][64][64] float4 (x,y,z,w)
    const float*  __restrict__ knot_u, // [B][68]
    float*        __restrict__ out)    // [B][256][256][3]
{
    const int b    = blockIdx.x / BPB;
    const int i0   = (blockIdx.x % BPB) * RPB;
    const int tid  = threadIdx.x;
    const int lane = tid & 31;
    const int wid  = tid >> 5;

    __shared__ float  U[LKNOT];
    __shared__ float  warpsum[2];
    __shared__ float4 cols4[RPB][NCTRL];   // 8 KB: (x,y,z,pad) u-contracted

    // ---- parallel inclusive cumsum of the 68 raw knot increments ----
    {
        float v = (tid < LKNOT) ? knot_u[b * LKNOT + tid] : 0.f;
        #pragma unroll
        for (int off = 1; off < 32; off <<= 1) {
            float n = __shfl_up_sync(0xffffffffu, v, off);
            if (lane >= off) v += n;
        }
        if (lane == 31 && wid < 2) warpsum[wid] = v;
        __syncthreads();
        if (wid == 1)      v += warpsum[0];
        else if (wid == 2) v += warpsum[0] + warpsum[1];
        if (tid < LKNOT) U[tid] = v;
        __syncthreads();
    }

    const float c0  = U[0];
    const float den = U[LKNOT - 1] - c0;
    const float thr = 1e-8f * den;
    const float step01 = (float)((1.0 - 2e-5) / 255.0);

    // ---- phase 1, item 0: rows i0..i0+3 ----
    const int ri0 = tid >> 6;            // 0..3
    const int cc  = tid & 63;            // 0..63
    {
        const int   i     = i0 + ri0;
        const float t_row = c0 + fmaf((float)i, step01, 1e-5f) * den;
        const int   srow  = find_span(U, t_row, thr);

        const float4* cp = ctrl + ((size_t)(b * MCTRL) + (srow - 3)) * NCTRL + cc;
        float4 p0 = cp[0 * NCTRL];
        float4 p1 = cp[1 * NCTRL];
        float4 p2 = cp[2 * NCTRL];
        float4 p3 = cp[3 * NCTRL];

        const float4 nu = cox_de_boor(U, t_row, srow);   // overlaps loads
        float4 r;
        r.x = fmaf(nu.x, p0.x, fmaf(nu.y, p1.x, fmaf(nu.z, p2.x, nu.w * p3.x)));
        r.y = fmaf(nu.x, p0.y, fmaf(nu.y, p1.y, fmaf(nu.z, p2.y, nu.w * p3.y)));
        r.z = fmaf(nu.x, p0.z, fmaf(nu.y, p1.z, fmaf(nu.z, p2.z, nu.w * p3.z)));
        r.w = 0.f;
        cols4[ri0][cc] = r;
    }

    // ---- own (v-role) span + basis for output column j = tid ----
    const int   j     = tid;
    const float t_own = c0 + fmaf((float)j, step01, 1e-5f) * den;
    const int   sj    = find_span(U, t_own, thr) - 3;
    const float4 nv   = cox_de_boor(U, t_own, sj + 3);

    // ---- phase 1, item 1: rows i0+4..i0+7 ----
    {
        const int   i     = i0 + 4 + ri0;
        const float t_row = c0 + fmaf((float)i, step01, 1e-5f) * den;
        const int   srow  = find_span(U, t_row, thr);

        const float4* cp = ctrl + ((size_t)(b * MCTRL) + (srow - 3)) * NCTRL + cc;
        float4 p0 = cp[0 * NCTRL];
        float4 p1 = cp[1 * NCTRL];
        float4 p2 = cp[2 * NCTRL];
        float4 p3 = cp[3 * NCTRL];

        const float4 nu = cox_de_boor(U, t_row, srow);
        float4 r;
        r.x = fmaf(nu.x, p0.x, fmaf(nu.y, p1.x, fmaf(nu.z, p2.x, nu.w * p3.x)));
        r.y = fmaf(nu.x, p0.y, fmaf(nu.y, p1.y, fmaf(nu.z, p2.y, nu.w * p3.y)));
        r.z = fmaf(nu.x, p0.z, fmaf(nu.y, p1.z, fmaf(nu.z, p2.z, nu.w * p3.z)));
        r.w = 0.f;
        cols4[4 + ri0][cc] = r;
    }

    __syncthreads();   // single post-scan barrier: cols publish

    // ---- phase 2: v-contraction, 8 independent rows per thread ----
    #pragma unroll
    for (int r = 0; r < RPB; r++) {
        float4 a = cols4[r][sj];
        float4 bb = cols4[r][sj + 1];
        float4 cq = cols4[r][sj + 2];
        float4 d = cols4[r][sj + 3];

        float x = fmaf(nv.x, a.x, fmaf(nv.y, bb.x, fmaf(nv.z, cq.x, nv.w * d.x)));
        float y = fmaf(nv.x, a.y, fmaf(nv.y, bb.y, fmaf(nv.z, cq.y, nv.w * d.y)));
        float z = fmaf(nv.x, a.z, fmaf(nv.y, bb.z, fmaf(nv.z, cq.z, nv.w * d.z)));

        float* o = out + ((size_t)((b * TOUT) + i0 + r) * TOUT + j) * 3;
        o[0] = x;
        o[1] = y;
        o[2] = z;
    }
}

// ---------------------------------------------------------------------------
// Launch. Inputs: d_in[0]=ctrl_pts [16,64,64,4] f32, d_in[1]=knot_u [16,68],
// d_in[2]=knot_v (UNUSED — reference builds V from knot_u).
// Output: [16,256,256,3] f32.
// ---------------------------------------------------------------------------
extern "C" void kernel_launch(void* const* d_in, const int* in_sizes, int n_in,
                              void* d_out, int out_size)
{
    const float4* ctrl   = (const float4*)d_in[0];
    const float*  knot_u = (const float*) d_in[1];
    float*        out    = (float*)d_out;

    SurfEval_fused_kernel<<<BATCH * BPB, THREADS>>>(ctrl, knot_u, out);
}